// round 4
// baseline (speedup 1.0000x reference)
#include <cuda_runtime.h>
#include <math.h>

#define C 64
#define NPIX 16384
#define BATCH 32
#define NCHUNK 16
#define CHUNK (NPIX / NCHUNK)   // 1024
#define TILE_N 32

// Scratch (allocation-free: __device__ globals)
__device__ float g_Wg[C * C];                          // gamma * W / sigma
__device__ float g_Mpart[NCHUNK * BATCH * C * C];      // Gram partials (8 MB)
__device__ float g_P[BATCH * C * C];                   // per-batch (gamma*M*Wg + I)

// ---------------------------------------------------------------------------
// Kernel 1: spectral norm power iteration -> g_Wg = gamma * W / sigma
// ---------------------------------------------------------------------------
__global__ void k_spectral(const float* __restrict__ W,
                           const float* __restrict__ gamma,
                           const float* __restrict__ u) {
    __shared__ float Ws[C][C];
    __shared__ float red[C];
    __shared__ float vs[C];
    const int t = threadIdx.x;  // 64 threads

    for (int r = 0; r < C; ++r) Ws[r][t] = W[r * C + t];
    __syncthreads();

    // v = l2norm(W^T u)
    float tv = 0.f;
    for (int r = 0; r < C; ++r) tv += Ws[r][t] * u[r];
    red[t] = tv * tv;
    __syncthreads();
    if (t == 0) {
        float s = 0.f;
        for (int i = 0; i < C; ++i) s += red[i];
        red[0] = sqrtf(s);
    }
    __syncthreads();
    const float vnorm = fmaxf(red[0], 1e-12f);
    vs[t] = tv / vnorm;
    __syncthreads();

    // wv = W v ; nrm = ||wv|| ; sigma = (wv/max(nrm,eps)) . wv = nrm^2/max(nrm,eps)
    float wv = 0.f;
    for (int c2 = 0; c2 < C; ++c2) wv += Ws[t][c2] * vs[c2];
    red[t] = wv * wv;
    __syncthreads();
    if (t == 0) {
        float s = 0.f;
        for (int i = 0; i < C; ++i) s += red[i];
        red[0] = sqrtf(s);
    }
    __syncthreads();
    const float nrm = red[0];
    const float sigma = (nrm * nrm) / fmaxf(nrm, 1e-12f);
    const float scale = gamma[0] / sigma;
    for (int c2 = 0; c2 < C; ++c2) g_Wg[t * C + c2] = Ws[t][c2] * scale;
}

// ---------------------------------------------------------------------------
// Kernel 2: Gram partials. grid = (NCHUNK, BATCH), 256 threads.
// Block computes full 64x64 Gram of its 1024-column chunk.
// smem tile stored transposed [n][c] (pitch 68) -> conflict-free LDS.128.
// ---------------------------------------------------------------------------
__global__ void __launch_bounds__(256) k_gram(const float* __restrict__ x) {
    const int chunk = blockIdx.x;
    const int b = blockIdx.y;
    const float* xb = x + (size_t)b * C * NPIX + (size_t)chunk * CHUNK;

    __shared__ float sm[TILE_N][68];

    const int tid = threadIdx.x;
    const int tx = tid & 15;
    const int ty = tid >> 4;
    const int lc = tid & 63;    // loader: channel row
    const int lseg = tid >> 6;  // loader: n-segment (0..3), fixed per warp pair

    float acc[4][4];
#pragma unroll
    for (int i = 0; i < 4; ++i)
#pragma unroll
        for (int j = 0; j < 4; ++j) acc[i][j] = 0.f;

    for (int t0 = 0; t0 < CHUNK; t0 += TILE_N) {
        __syncthreads();
        const float* src = xb + (size_t)lc * NPIX + t0 + lseg * 8;
        const float4 v0 = *(const float4*)(src);
        const float4 v1 = *(const float4*)(src + 4);
        const int nb = lseg * 8;
        sm[nb + 0][lc] = v0.x; sm[nb + 1][lc] = v0.y;
        sm[nb + 2][lc] = v0.z; sm[nb + 3][lc] = v0.w;
        sm[nb + 4][lc] = v1.x; sm[nb + 5][lc] = v1.y;
        sm[nb + 6][lc] = v1.z; sm[nb + 7][lc] = v1.w;
        __syncthreads();

#pragma unroll
        for (int n = 0; n < TILE_N; ++n) {
            const float4 a4 = *(const float4*)&sm[n][4 * ty];
            const float4 b4 = *(const float4*)&sm[n][4 * tx];
            const float av[4] = {a4.x, a4.y, a4.z, a4.w};
            const float bv[4] = {b4.x, b4.y, b4.z, b4.w};
#pragma unroll
            for (int i = 0; i < 4; ++i)
#pragma unroll
                for (int j = 0; j < 4; ++j) acc[i][j] += av[i] * bv[j];
        }
    }

    float* dst = g_Mpart + ((size_t)(chunk * BATCH + b)) * C * C;
#pragma unroll
    for (int i = 0; i < 4; ++i)
#pragma unroll
        for (int j = 0; j < 4; ++j)
            dst[(4 * ty + i) * C + 4 * tx + j] = acc[i][j];
}

// ---------------------------------------------------------------------------
// Kernel 3: reduce Gram partials, P_b = M_b @ Wg + I. grid = BATCH.
// ---------------------------------------------------------------------------
__global__ void __launch_bounds__(256) k_P(void) {
    const int b = blockIdx.x;
    __shared__ float Ms[C][65];
    __shared__ float Wgs[C][65];
    const int tid = threadIdx.x;

    for (int i = tid; i < C * C; i += 256) {
        float s = 0.f;
#pragma unroll
        for (int k = 0; k < NCHUNK; ++k)
            s += g_Mpart[((size_t)(k * BATCH + b)) * C * C + i];
        Ms[i >> 6][i & 63] = s;
        Wgs[i >> 6][i & 63] = g_Wg[i];
    }
    __syncthreads();

    for (int i = tid; i < C * C; i += 256) {
        const int c = i >> 6, e = i & 63;
        float s = (c == e) ? 1.0f : 0.0f;
#pragma unroll
        for (int d = 0; d < C; ++d) s += Ms[c][d] * Wgs[d][e];
        g_P[(size_t)b * C * C + i] = s;
    }
}

// ---------------------------------------------------------------------------
// Kernel 4: out[b,c,n] = sum_e P[b,c,e] * x[b,e,n].
// grid = (NPIX/128, BATCH), 256 threads; block tile = 64c x 128n, thread 4x8.
// ---------------------------------------------------------------------------
__global__ void __launch_bounds__(256) k_out(const float* __restrict__ x,
                                             float* __restrict__ out) {
    const int n0 = blockIdx.x * 128;
    const int b = blockIdx.y;
    const float* xb = x + (size_t)b * C * NPIX + n0;
    float* ob = out + (size_t)b * C * NPIX + n0;

    __shared__ float Ps[C][65];
    __shared__ float xt[16][132];

    const int tid = threadIdx.x;
    const int tx = tid & 15;
    const int ty = tid >> 4;
    const int le = tid >> 4;   // loader e-row 0..15
    const int lc4 = tid & 15;  // loader col group

    const float* Pb = g_P + (size_t)b * C * C;
    for (int i = tid; i < C * C; i += 256)
        Ps[i >> 6][i & 63] = Pb[i];

    float acc[4][8];
#pragma unroll
    for (int i = 0; i < 4; ++i)
#pragma unroll
        for (int j = 0; j < 8; ++j) acc[i][j] = 0.f;

    for (int et = 0; et < 4; ++et) {
        __syncthreads();
        const float* src = xb + (size_t)(et * 16 + le) * NPIX;
        *(float4*)&xt[le][4 * lc4] = *(const float4*)(src + 4 * lc4);
        *(float4*)&xt[le][4 * lc4 + 64] = *(const float4*)(src + 4 * lc4 + 64);
        __syncthreads();

#pragma unroll
        for (int ee = 0; ee < 16; ++ee) {
            const int e = et * 16 + ee;
            const float4 b0 = *(const float4*)&xt[ee][4 * tx];
            const float4 b1 = *(const float4*)&xt[ee][4 * tx + 64];
#pragma unroll
            for (int i = 0; i < 4; ++i) {
                const float p = Ps[4 * ty + i][e];
                acc[i][0] += p * b0.x; acc[i][1] += p * b0.y;
                acc[i][2] += p * b0.z; acc[i][3] += p * b0.w;
                acc[i][4] += p * b1.x; acc[i][5] += p * b1.y;
                acc[i][6] += p * b1.z; acc[i][7] += p * b1.w;
            }
        }
    }

#pragma unroll
    for (int i = 0; i < 4; ++i) {
        const float4 o0 = make_float4(acc[i][0], acc[i][1], acc[i][2], acc[i][3]);
        const float4 o1 = make_float4(acc[i][4], acc[i][5], acc[i][6], acc[i][7]);
        *(float4*)(ob + (size_t)(4 * ty + i) * NPIX + 4 * tx) = o0;
        *(float4*)(ob + (size_t)(4 * ty + i) * NPIX + 4 * tx + 64) = o1;
    }
}

// ---------------------------------------------------------------------------
extern "C" void kernel_launch(void* const* d_in, const int* in_sizes, int n_in,
                              void* d_out, int out_size) {
    const float* x = (const float*)d_in[0];
    const float* W = (const float*)d_in[1];
    const float* gamma = (const float*)d_in[2];
    const float* u = (const float*)d_in[3];
    float* out = (float*)d_out;

    k_spectral<<<1, 64>>>(W, gamma, u);

    dim3 gg(NCHUNK, BATCH);
    k_gram<<<gg, 256>>>(x);

    k_P<<<BATCH, 256>>>();

    dim3 go(NPIX / 128, BATCH);
    k_out<<<go, 256>>>(x, out);
}

// round 5
// speedup vs baseline: 1.0507x; 1.0507x over previous
#include <cuda_runtime.h>
#include <math.h>

#define C 64
#define NPIX 16384
#define BATCH 32
#define NCHUNK 16
#define CHUNK (NPIX / NCHUNK)   // 1024
#define TILE_N 32

// Scratch (allocation-free: __device__ globals)
__device__ float g_Wg[C * C];                          // gamma * W / sigma
__device__ float g_Mpart[NCHUNK * BATCH * C * C];      // Gram partials (8 MB)
__device__ float g_P[BATCH * C * C];                   // per-batch (gamma*M*Wg + I)

// ---------------------------------------------------------------------------
// Packed f32x2 helpers (sm_103a FFMA2 path — ptxas won't emit from C++)
// ---------------------------------------------------------------------------
__device__ __forceinline__ unsigned long long fma2(unsigned long long a,
                                                   unsigned long long b,
                                                   unsigned long long c) {
    unsigned long long d;
    asm("fma.rn.f32x2 %0, %1, %2, %3;" : "=l"(d) : "l"(a), "l"(b), "l"(c));
    return d;
}
__device__ __forceinline__ unsigned long long bcast2(float p) {
    unsigned long long d;
    asm("mov.b64 %0, {%1, %1};" : "=l"(d) : "r"(__float_as_uint(p)));
    return d;
}

// ---------------------------------------------------------------------------
// Kernel 1: spectral norm power iteration -> g_Wg = gamma * W / sigma
// ---------------------------------------------------------------------------
__global__ void k_spectral(const float* __restrict__ W,
                           const float* __restrict__ gamma,
                           const float* __restrict__ u) {
    __shared__ float Ws[C][C];
    __shared__ float red[C];
    __shared__ float vs[C];
    const int t = threadIdx.x;  // 64 threads

    for (int r = 0; r < C; ++r) Ws[r][t] = W[r * C + t];
    __syncthreads();

    // v = l2norm(W^T u)
    float tv = 0.f;
    for (int r = 0; r < C; ++r) tv += Ws[r][t] * u[r];
    red[t] = tv * tv;
    __syncthreads();
    if (t == 0) {
        float s = 0.f;
        for (int i = 0; i < C; ++i) s += red[i];
        red[0] = sqrtf(s);
    }
    __syncthreads();
    const float vnorm = fmaxf(red[0], 1e-12f);
    vs[t] = tv / vnorm;
    __syncthreads();

    // wv = W v ; sigma = ||wv||^2 / max(||wv||, eps)
    float wv = 0.f;
    for (int c2 = 0; c2 < C; ++c2) wv += Ws[t][c2] * vs[c2];
    red[t] = wv * wv;
    __syncthreads();
    if (t == 0) {
        float s = 0.f;
        for (int i = 0; i < C; ++i) s += red[i];
        red[0] = sqrtf(s);
    }
    __syncthreads();
    const float nrm = red[0];
    const float sigma = (nrm * nrm) / fmaxf(nrm, 1e-12f);
    const float scale = gamma[0] / sigma;
    for (int c2 = 0; c2 < C; ++c2) g_Wg[t * C + c2] = Ws[t][c2] * scale;
}

// ---------------------------------------------------------------------------
// Kernel 2: Gram partials, upper-triangle tiles only + FFMA2.
// grid = (NCHUNK, BATCH), 256 threads. 136 active threads own one 4x4 tile
// (i<=j) of the 64x64 Gram; epilogue mirrors into the lower triangle.
// ---------------------------------------------------------------------------
__global__ void __launch_bounds__(256) k_gram(const float* __restrict__ x) {
    const int chunk = blockIdx.x;
    const int b = blockIdx.y;
    const float* xb = x + (size_t)b * C * NPIX + (size_t)chunk * CHUNK;

    __shared__ float sm[TILE_N][68];

    const int tid = threadIdx.x;
    const int lc = tid & 63;    // loader: channel row
    const int lseg = tid >> 6;  // loader: n-segment (0..3)

    // map tid -> upper-triangle tile (ti, tj), ti <= tj, 136 tiles
    const bool active = tid < 136;
    int ti = 0, rem = active ? tid : 0;
    while (rem >= 16 - ti) { rem -= 16 - ti; ++ti; }
    const int tj = ti + rem;

    unsigned long long acc[4][2];  // 4 rows x (2 f32x2 pairs = 4 cols)
#pragma unroll
    for (int i = 0; i < 4; ++i) { acc[i][0] = 0ull; acc[i][1] = 0ull; }

    for (int t0 = 0; t0 < CHUNK; t0 += TILE_N) {
        __syncthreads();
        const float* src = xb + (size_t)lc * NPIX + t0 + lseg * 8;
        const float4 v0 = *(const float4*)(src);
        const float4 v1 = *(const float4*)(src + 4);
        const int nb = lseg * 8;
        sm[nb + 0][lc] = v0.x; sm[nb + 1][lc] = v0.y;
        sm[nb + 2][lc] = v0.z; sm[nb + 3][lc] = v0.w;
        sm[nb + 4][lc] = v1.x; sm[nb + 5][lc] = v1.y;
        sm[nb + 6][lc] = v1.z; sm[nb + 7][lc] = v1.w;
        __syncthreads();

        if (active) {
#pragma unroll
            for (int n = 0; n < TILE_N; ++n) {
                const float4 a4 = *(const float4*)&sm[n][4 * ti];
                const ulonglong2 b2 = *(const ulonglong2*)&sm[n][4 * tj];
                const unsigned long long p0 = bcast2(a4.x);
                const unsigned long long p1 = bcast2(a4.y);
                const unsigned long long p2 = bcast2(a4.z);
                const unsigned long long p3 = bcast2(a4.w);
                acc[0][0] = fma2(p0, b2.x, acc[0][0]);
                acc[0][1] = fma2(p0, b2.y, acc[0][1]);
                acc[1][0] = fma2(p1, b2.x, acc[1][0]);
                acc[1][1] = fma2(p1, b2.y, acc[1][1]);
                acc[2][0] = fma2(p2, b2.x, acc[2][0]);
                acc[2][1] = fma2(p2, b2.y, acc[2][1]);
                acc[3][0] = fma2(p3, b2.x, acc[3][0]);
                acc[3][1] = fma2(p3, b2.y, acc[3][1]);
            }
        }
    }

    if (active) {
        float* dst = g_Mpart + ((size_t)(chunk * BATCH + b)) * C * C;
#pragma unroll
        for (int ii = 0; ii < 4; ++ii) {
            const float2 f0 = *reinterpret_cast<float2*>(&acc[ii][0]);
            const float2 f1 = *reinterpret_cast<float2*>(&acc[ii][1]);
            const int r = 4 * ti + ii;
            const int cbase = 4 * tj;
            dst[r * C + cbase + 0] = f0.x;
            dst[r * C + cbase + 1] = f0.y;
            dst[r * C + cbase + 2] = f1.x;
            dst[r * C + cbase + 3] = f1.y;
            if (ti != tj) {
                dst[(cbase + 0) * C + r] = f0.x;
                dst[(cbase + 1) * C + r] = f0.y;
                dst[(cbase + 2) * C + r] = f1.x;
                dst[(cbase + 3) * C + r] = f1.y;
            }
        }
    }
}

// ---------------------------------------------------------------------------
// Kernel 3: reduce Gram partials, P_b = M_b @ Wg + I. grid = BATCH.
// ---------------------------------------------------------------------------
__global__ void __launch_bounds__(256) k_P(void) {
    const int b = blockIdx.x;
    __shared__ float Ms[C][65];
    __shared__ float Wgs[C][65];
    const int tid = threadIdx.x;

    for (int i = tid; i < C * C; i += 256) {
        float s = 0.f;
#pragma unroll
        for (int k = 0; k < NCHUNK; ++k)
            s += g_Mpart[((size_t)(k * BATCH + b)) * C * C + i];
        Ms[i >> 6][i & 63] = s;
        Wgs[i >> 6][i & 63] = g_Wg[i];
    }
    __syncthreads();

    for (int i = tid; i < C * C; i += 256) {
        const int c = i >> 6, e = i & 63;
        float s = (c == e) ? 1.0f : 0.0f;
#pragma unroll
        for (int d = 0; d < C; ++d) s += Ms[c][d] * Wgs[d][e];
        g_P[(size_t)b * C * C + i] = s;
    }
}

// ---------------------------------------------------------------------------
// Kernel 4: out[b,c,n] = sum_e P[b,c,e] * x[b,e,n]  (FFMA2 inner loop).
// grid = (NPIX/128, BATCH), 256 threads; block tile = 64c x 128n, thread 4x8.
// ---------------------------------------------------------------------------
__global__ void __launch_bounds__(256) k_out(const float* __restrict__ x,
                                             float* __restrict__ out) {
    const int n0 = blockIdx.x * 128;
    const int b = blockIdx.y;
    const float* xb = x + (size_t)b * C * NPIX + n0;
    float* ob = out + (size_t)b * C * NPIX + n0;

    __shared__ float Ps[C][65];
    __shared__ float xt[16][132];

    const int tid = threadIdx.x;
    const int tx = tid & 15;
    const int ty = tid >> 4;
    const int le = tid >> 4;   // loader e-row 0..15
    const int lc4 = tid & 15;  // loader col group

    const float* Pb = g_P + (size_t)b * C * C;
    for (int i = tid; i < C * C; i += 256)
        Ps[i >> 6][i & 63] = Pb[i];

    unsigned long long acc[4][4];  // 4 c-rows x (4 f32x2 pairs = 8 n-cols)
#pragma unroll
    for (int i = 0; i < 4; ++i)
#pragma unroll
        for (int j = 0; j < 4; ++j) acc[i][j] = 0ull;

    for (int et = 0; et < 4; ++et) {
        __syncthreads();
        const float* src = xb + (size_t)(et * 16 + le) * NPIX;
        *(float4*)&xt[le][4 * lc4] = *(const float4*)(src + 4 * lc4);
        *(float4*)&xt[le][4 * lc4 + 64] = *(const float4*)(src + 4 * lc4 + 64);
        __syncthreads();

#pragma unroll
        for (int ee = 0; ee < 16; ++ee) {
            const int e = et * 16 + ee;
            const ulonglong2 b0 = *(const ulonglong2*)&xt[ee][4 * tx];
            const ulonglong2 b1 = *(const ulonglong2*)&xt[ee][4 * tx + 64];
#pragma unroll
            for (int i = 0; i < 4; ++i) {
                const unsigned long long pp = bcast2(Ps[4 * ty + i][e]);
                acc[i][0] = fma2(pp, b0.x, acc[i][0]);
                acc[i][1] = fma2(pp, b0.y, acc[i][1]);
                acc[i][2] = fma2(pp, b1.x, acc[i][2]);
                acc[i][3] = fma2(pp, b1.y, acc[i][3]);
            }
        }
    }

#pragma unroll
    for (int i = 0; i < 4; ++i) {
        const float2 a0 = *reinterpret_cast<float2*>(&acc[i][0]);
        const float2 a1 = *reinterpret_cast<float2*>(&acc[i][1]);
        const float2 a2 = *reinterpret_cast<float2*>(&acc[i][2]);
        const float2 a3 = *reinterpret_cast<float2*>(&acc[i][3]);
        const float4 o0 = make_float4(a0.x, a0.y, a1.x, a1.y);
        const float4 o1 = make_float4(a2.x, a2.y, a3.x, a3.y);
        *(float4*)(ob + (size_t)(4 * ty + i) * NPIX + 4 * tx) = o0;
        *(float4*)(ob + (size_t)(4 * ty + i) * NPIX + 4 * tx + 64) = o1;
    }
}

// ---------------------------------------------------------------------------
extern "C" void kernel_launch(void* const* d_in, const int* in_sizes, int n_in,
                              void* d_out, int out_size) {
    const float* x = (const float*)d_in[0];
    const float* W = (const float*)d_in[1];
    const float* gamma = (const float*)d_in[2];
    const float* u = (const float*)d_in[3];
    float* out = (float*)d_out;

    k_spectral<<<1, 64>>>(W, gamma, u);

    dim3 gg(NCHUNK, BATCH);
    k_gram<<<gg, 256>>>(x);

    k_P<<<BATCH, 256>>>();

    dim3 go(NPIX / 128, BATCH);
    k_out<<<go, 256>>>(x, out);
}

// round 9
// speedup vs baseline: 1.7804x; 1.6945x over previous
#include <cuda_runtime.h>
#include <cuda_bf16.h>
#include <math.h>
#include <stdint.h>

#define C 64
#define NPIX 16384
#define BATCH 32
#define GCHUNK 16               // gram chunks per batch
#define GK (NPIX / GCHUNK)      // 1024 pixels per gram CTA
#define OTILE 64                // k_out pixels per CTA

// ---------------- scratch (__device__ globals; allocation-free) -------------
__device__ float g_Wg[C * C];                        // gamma*W/sigma
__device__ float g_Mpart[BATCH * GCHUNK * 128 * 64]; // Gram partials (16.8 MB)
__device__ __nv_bfloat16 g_Pb[BATCH * 64 * 128];     // [Ph | Pl] per batch

// ---------------- PTX helpers ----------------------------------------------
__device__ __forceinline__ void ldsm_x4(uint32_t (&r)[4], uint32_t addr) {
    asm volatile("ldmatrix.sync.aligned.m8n8.x4.shared.b16 {%0,%1,%2,%3}, [%4];"
                 : "=r"(r[0]), "=r"(r[1]), "=r"(r[2]), "=r"(r[3]) : "r"(addr));
}
__device__ __forceinline__ void ldsm_x2(uint32_t (&r)[2], uint32_t addr) {
    asm volatile("ldmatrix.sync.aligned.m8n8.x2.shared.b16 {%0,%1}, [%2];"
                 : "=r"(r[0]), "=r"(r[1]) : "r"(addr));
}
__device__ __forceinline__ void ldsm_x2t(uint32_t (&r)[2], uint32_t addr) {
    asm volatile("ldmatrix.sync.aligned.m8n8.x2.trans.shared.b16 {%0,%1}, [%2];"
                 : "=r"(r[0]), "=r"(r[1]) : "r"(addr));
}
__device__ __forceinline__ void mma16816(float (&d)[4], const uint32_t (&a)[4],
                                         const uint32_t (&b)[2]) {
    asm volatile(
        "mma.sync.aligned.m16n8k16.row.col.f32.bf16.bf16.f32 "
        "{%0,%1,%2,%3}, {%4,%5,%6,%7}, {%8,%9}, {%0,%1,%2,%3};"
        : "+f"(d[0]), "+f"(d[1]), "+f"(d[2]), "+f"(d[3])
        : "r"(a[0]), "r"(a[1]), "r"(a[2]), "r"(a[3]), "r"(b[0]), "r"(b[1]));
}

union BPack { __nv_bfloat162 h2[2]; uint2 u; };

// split one float4 into hi/lo bf16 packs
__device__ __forceinline__ void split4(const float4 v, BPack& hp, BPack& lp) {
    const float f[4] = {v.x, v.y, v.z, v.w};
    __nv_bfloat16 h[4], l[4];
#pragma unroll
    for (int j = 0; j < 4; ++j) {
        h[j] = __float2bfloat16(f[j]);
        l[j] = __float2bfloat16(f[j] - __bfloat162float(h[j]));
    }
    hp.h2[0] = __halves2bfloat162(h[0], h[1]);
    hp.h2[1] = __halves2bfloat162(h[2], h[3]);
    lp.h2[0] = __halves2bfloat162(l[0], l[1]);
    lp.h2[1] = __halves2bfloat162(l[2], l[3]);
}

// ---------------------------------------------------------------------------
// Kernel 1: spectral norm power iteration -> g_Wg = gamma * W / sigma
// ---------------------------------------------------------------------------
__global__ void k_spectral(const float* __restrict__ W,
                           const float* __restrict__ gamma,
                           const float* __restrict__ u) {
    __shared__ float Ws[C][C];
    __shared__ float red[C];
    __shared__ float vs[C];
    const int t = threadIdx.x;  // 64 threads

    for (int r = 0; r < C; ++r) Ws[r][t] = W[r * C + t];
    __syncthreads();

    float tv = 0.f;
    for (int r = 0; r < C; ++r) tv += Ws[r][t] * u[r];
    red[t] = tv * tv;
    __syncthreads();
    if (t == 0) {
        float s = 0.f;
        for (int i = 0; i < C; ++i) s += red[i];
        red[0] = sqrtf(s);
    }
    __syncthreads();
    const float vnorm = fmaxf(red[0], 1e-12f);
    vs[t] = tv / vnorm;
    __syncthreads();

    float wv = 0.f;
    for (int c2 = 0; c2 < C; ++c2) wv += Ws[t][c2] * vs[c2];
    red[t] = wv * wv;
    __syncthreads();
    if (t == 0) {
        float s = 0.f;
        for (int i = 0; i < C; ++i) s += red[i];
        red[0] = sqrtf(s);
    }
    __syncthreads();
    const float nrm = red[0];
    const float sigma = (nrm * nrm) / fmaxf(nrm, 1e-12f);
    const float scale = gamma[0] / sigma;
    for (int c2 = 0; c2 < C; ++c2) g_Wg[t * C + c2] = Ws[t][c2] * scale;
}

// ---------------------------------------------------------------------------
// Kernel 2: on-the-fly (xh, xl) split in smem; Gram partials
// D = [xh;xl] @ xh^T (128x64) via mma.sync bf16.
// M is later assembled as Dhh + Dlh + Dlh^T (both cross terms present).
// grid = (GCHUNK, BATCH), 256 threads (8 warps: 4 m-tiles x 2 n-tiles).
// ---------------------------------------------------------------------------
__global__ void __launch_bounds__(256) k_gram(const float* __restrict__ x) {
    const int chunk = blockIdx.x;
    const int b = blockIdx.y;
    const float* xb = x + (size_t)b * C * NPIX + chunk * GK;

    __shared__ __align__(16) __nv_bfloat16 sa[128][72];  // [hi 0-63 | lo 64-127] x 64 px
    const int tid = threadIdx.x;
    const int lane = tid & 31;
    const int w = tid >> 5;
    const int wm = w & 3;   // m tile: rows 32*wm
    const int wn = w >> 2;  // n tile: cols 32*wn
    const uint32_t sa_base = (uint32_t)__cvta_generic_to_shared(&sa[0][0]);

    float acc[2][4][4] = {};

    for (int p0 = 0; p0 < GK; p0 += 64) {
        __syncthreads();  // previous iter's reads done before overwrite
#pragma unroll
        for (int i = 0; i < 4; ++i) {
            const int idx = tid + 256 * i;
            const int ch = idx >> 4;
            const int cg = idx & 15;
            const float4 v = *(const float4*)(xb + (size_t)ch * NPIX + p0 + 4 * cg);
            BPack hp, lp;
            split4(v, hp, lp);
            *(uint2*)&sa[ch][4 * cg] = hp.u;
            *(uint2*)&sa[ch + 64][4 * cg] = lp.u;
        }
        __syncthreads();

#pragma unroll
        for (int ks = 0; ks < 4; ++ks) {
            uint32_t a[2][4];
            uint32_t bf[4][2];
#pragma unroll
            for (int mi = 0; mi < 2; ++mi)
                ldsm_x4(a[mi], sa_base +
                        2u * ((uint32_t)(32 * wm + 16 * mi + (lane & 15)) * 72 +
                              16 * ks + 8 * (lane >> 4)));
#pragma unroll
            for (int ni = 0; ni < 4; ++ni)
                ldsm_x2(bf[ni], sa_base +
                        2u * ((uint32_t)(32 * wn + 8 * ni + (lane & 7)) * 72 +
                              16 * ks + 8 * ((lane >> 3) & 1)));
#pragma unroll
            for (int mi = 0; mi < 2; ++mi)
#pragma unroll
                for (int ni = 0; ni < 4; ++ni)
                    mma16816(acc[mi][ni], a[mi], bf[ni]);
        }
    }

    float* dst = g_Mpart + (size_t)(b * GCHUNK + chunk) * 128 * 64;
#pragma unroll
    for (int mi = 0; mi < 2; ++mi)
#pragma unroll
        for (int ni = 0; ni < 4; ++ni) {
            const int row = 32 * wm + 16 * mi + (lane >> 2);
            const int col = 32 * wn + 8 * ni + 2 * (lane & 3);
            *(float2*)&dst[row * 64 + col] = make_float2(acc[mi][ni][0], acc[mi][ni][1]);
            *(float2*)&dst[(row + 8) * 64 + col] = make_float2(acc[mi][ni][2], acc[mi][ni][3]);
        }
}

// ---------------------------------------------------------------------------
// Kernel 3: reduce partials, M = Dhh + Dlh + Dlh^T; P = M*Wg + I;
// split-store P as bf16 [Ph | Pl] (64 x 128). grid = BATCH.
// ---------------------------------------------------------------------------
__global__ void __launch_bounds__(256) k_P(void) {
    const int b = blockIdx.x;
    __shared__ float Ms[64][65];
    __shared__ float Wgs[64][65];
    const int tid = threadIdx.x;

    for (int i = tid; i < C * C; i += 256)
        Wgs[i >> 6][i & 63] = g_Wg[i];

    for (int i = tid; i < C * C; i += 256) {
        const int c = i >> 6, d = i & 63;
        float s = 0.f;
#pragma unroll
        for (int k = 0; k < GCHUNK; ++k) {
            const float* D = g_Mpart + (size_t)(b * GCHUNK + k) * 128 * 64;
            s += D[c * 64 + d] + D[(64 + c) * 64 + d] + D[(64 + d) * 64 + c];
        }
        Ms[c][d] = s;
    }
    __syncthreads();

    for (int i = tid; i < C * C; i += 256) {
        const int c = i >> 6, e = i & 63;
        float s = (c == e) ? 1.0f : 0.0f;
#pragma unroll
        for (int d = 0; d < C; ++d) s += Ms[c][d] * Wgs[d][e];
        const __nv_bfloat16 hi = __float2bfloat16(s);
        const __nv_bfloat16 lo = __float2bfloat16(s - __bfloat162float(hi));
        g_Pb[((size_t)b * 64 + c) * 128 + e] = hi;
        g_Pb[((size_t)b * 64 + c) * 128 + 64 + e] = lo;
    }
}

// ---------------------------------------------------------------------------
// Kernel 4: out = Ph@xh + Ph@xl + Pl@xh  (three bf16 pairings; only the
// O(2^-18) term Pl@xl is dropped). (xh,xl) split in-register from fp32 x.
// grid = (NPIX/OTILE, BATCH), 256 threads (warps: 4 m-tiles x 2 n-halves).
// ---------------------------------------------------------------------------
__global__ void __launch_bounds__(256) k_out(const float* __restrict__ x,
                                             float* __restrict__ out) {
    const int n0 = blockIdx.x * OTILE;
    const int b = blockIdx.y;
    const float* xb = x + (size_t)b * C * NPIX + n0;

    __shared__ __align__(16) __nv_bfloat16 sb[128][72];   // [xh ch 0-63 | xl ch 64-127]
    __shared__ __align__(16) __nv_bfloat16 sp[64][136];   // P tile [c=64][Ph k 0-63 | Pl 64-127]

    const int tid = threadIdx.x;
    const int lane = tid & 31;
    const int w = tid >> 5;
    const int wm = w & 3;   // m: rows 16*wm
    const int wn = w >> 2;  // n half: cols 32*wn
    const uint32_t sbb = (uint32_t)__cvta_generic_to_shared(&sb[0][0]);
    const uint32_t spb = (uint32_t)__cvta_generic_to_shared(&sp[0][0]);

    // load P tile (64 x 128 bf16) and split-convert x tile (64ch x 64px fp32)
#pragma unroll
    for (int i = 0; i < 4; ++i) {
        const int idx = tid + 256 * i;
        {
            const int row = idx >> 4, g = idx & 15;
            *(uint4*)&sp[row][8 * g] =
                *(const uint4*)&g_Pb[((size_t)b * 64 + row) * 128 + 8 * g];
        }
        {
            const int ch = idx >> 4, cg = idx & 15;
            const float4 v = *(const float4*)(xb + (size_t)ch * NPIX + 4 * cg);
            BPack hp, lp;
            split4(v, hp, lp);
            *(uint2*)&sb[ch][4 * cg] = hp.u;
            *(uint2*)&sb[ch + 64][4 * cg] = lp.u;
        }
    }
    __syncthreads();

    float acc[4][4] = {};
#pragma unroll
    for (int kk = 0; kk < 4; ++kk) {
        // A fragments: Ph (k-cols 16*kk) and Pl (k-cols 64 + 16*kk)
        uint32_t aph[4], apl[4];
        ldsm_x4(aph, spb + 2u * ((uint32_t)(16 * wm + (lane & 15)) * 136 +
                                 16 * kk + 8 * (lane >> 4)));
        ldsm_x4(apl, spb + 2u * ((uint32_t)(16 * wm + (lane & 15)) * 136 +
                                 64 + 16 * kk + 8 * (lane >> 4)));
#pragma unroll
        for (int ni = 0; ni < 4; ++ni) {
            uint32_t bh[2], bl[2];
            ldsm_x2t(bh, sbb + 2u * ((uint32_t)(16 * kk + (lane & 15)) * 72 +
                                     32 * wn + 8 * ni));
            ldsm_x2t(bl, sbb + 2u * ((uint32_t)(64 + 16 * kk + (lane & 15)) * 72 +
                                     32 * wn + 8 * ni));
            mma16816(acc[ni], aph, bh);   // Ph @ xh
            mma16816(acc[ni], aph, bl);   // Ph @ xl
            mma16816(acc[ni], apl, bh);   // Pl @ xh
        }
    }

    float* ob = out + (size_t)b * C * NPIX + n0;
#pragma unroll
    for (int ni = 0; ni < 4; ++ni) {
        const int row = 16 * wm + (lane >> 2);
        const int col = 32 * wn + 8 * ni + 2 * (lane & 3);
        *(float2*)&ob[(size_t)row * NPIX + col] = make_float2(acc[ni][0], acc[ni][1]);
        *(float2*)&ob[(size_t)(row + 8) * NPIX + col] = make_float2(acc[ni][2], acc[ni][3]);
    }
}

// ---------------------------------------------------------------------------
extern "C" void kernel_launch(void* const* d_in, const int* in_sizes, int n_in,
                              void* d_out, int out_size) {
    const float* x = (const float*)d_in[0];
    const float* W = (const float*)d_in[1];
    const float* gamma = (const float*)d_in[2];
    const float* u = (const float*)d_in[3];
    float* out = (float*)d_out;

    k_spectral<<<1, 64>>>(W, gamma, u);

    dim3 gg(GCHUNK, BATCH);
    k_gram<<<gg, 256>>>(x);

    k_P<<<BATCH, 256>>>();

    dim3 go(NPIX / OTILE, BATCH);
    k_out<<<go, 256>>>(x, out);
}